// round 15
// baseline (speedup 1.0000x reference)
#include <cuda_runtime.h>
#include <math.h>
#include <stdint.h>

#define NN 50000
#define EE 800000
#define HID 128
#define NH 4
#define LAY 3
#define NEG 0.2f
#define LN_EPS 1e-5f
#define LO_OFF (7 * 16384)

// ---------------- scratch ----------------
__device__ float  g_xl[NN * HID];
__device__ float  g_xr[NN * HID];
__device__ float  g_agg[NN * HID];
__device__ int    g_cnt[NN];
__device__ int    g_off[NN + 1];
__device__ int    g_cur[NN];
__device__ float4 g_edge[EE];             // {src_bits, a0, a1, a2}
__device__ float  g_stats[6];
__device__ int    g_bsum[256];
__device__ int    g_boff[256];
__device__ uint32_t g_wpack[14 * 16384];  // hi[7 mats] then lo[7 mats], tf32 fragment order

// ---------------- helpers ----------------
__device__ __forceinline__ uint32_t f2tf32(float v) {
    uint32_t o;
    asm("cvt.rna.tf32.f32 %0, %1;" : "=r"(o) : "f"(v));
    return o;
}

__device__ __forceinline__ void mma_tf32(float c[4], const uint32_t a[4], const uint32_t b[2]) {
    asm volatile(
        "mma.sync.aligned.m16n8k8.row.col.f32.tf32.tf32.f32 "
        "{%0,%1,%2,%3}, {%4,%5,%6,%7}, {%8,%9}, {%0,%1,%2,%3};\n"
        : "+f"(c[0]), "+f"(c[1]), "+f"(c[2]), "+f"(c[3])
        : "r"(a[0]), "r"(a[1]), "r"(a[2]), "r"(a[3]), "r"(b[0]), "r"(b[1]));
}

__device__ __forceinline__ int incl_scan256(int v) {
    int lane = threadIdx.x & 31, w = threadIdx.x >> 5;
    #pragma unroll
    for (int o = 1; o < 32; o <<= 1) {
        int n = __shfl_up_sync(0xffffffffu, v, o);
        if (lane >= o) v += n;
    }
    __shared__ int ws[8];
    if (lane == 31) ws[w] = v;
    __syncthreads();
    int add = 0;
    #pragma unroll
    for (int i = 0; i < 8; i++) if (i < w) add += ws[i];
    __syncthreads();
    return v + add;
}

// ---------------- weight pack (tf32 hi/lo, fragment order) + zero duties ----------------
__global__ void pack_kernel(const float* __restrict__ Wl, const float* __restrict__ Wr,
                            const float* __restrict__ Wout, uint32_t* __restrict__ P) {
    int idx = blockIdx.x * 256 + threadIdx.x;
    if (idx < NN) g_cnt[idx] = 0;
    if (idx < 6) g_stats[idx] = 0.f;
    if (idx == 6) g_off[NN] = EE;
    if (idx >= 7 * 16384) return;
    int mat = idx >> 14;
    int r = idx & 16383;
    int kt   = r >> 10;
    int nt   = (r >> 6) & 15;
    int lane = (r >> 1) & 31;
    int reg  = r & 1;
    int k = kt * 8 + (lane & 3) + reg * 4;
    int n = nt * 8 + (lane >> 2);
    const float* W = (mat < 3) ? (Wl + mat * 16384)
                   : (mat < 6) ? (Wr + (mat - 3) * 16384)
                               : Wout;
    float w = W[k * 128 + n];
    uint32_t hi = f2tf32(w);
    P[idx] = hi;
    P[idx + LO_OFF] = f2tf32(w - __uint_as_float(hi));
}

// ---------------- CSR build ----------------
__global__ void hist_kernel(const int* __restrict__ ei) {
    int e = blockIdx.x * blockDim.x + threadIdx.x;
    if (e >= EE) return;
    atomicAdd(&g_cnt[ei[EE + e]], 1);
}

__global__ void blocksum_kernel() {
    __shared__ int sh[256];
    int i = blockIdx.x * 256 + threadIdx.x;
    sh[threadIdx.x] = (i < NN) ? g_cnt[i] : 0;
    __syncthreads();
    for (int d = 128; d > 0; d >>= 1) {
        if (threadIdx.x < d) sh[threadIdx.x] += sh[threadIdx.x + d];
        __syncthreads();
    }
    if (threadIdx.x == 0) g_bsum[blockIdx.x] = sh[0];
}

__global__ void bscan_kernel(int nblk) {
    int t = threadIdx.x;
    int v = (t < nblk) ? g_bsum[t] : 0;
    int incl = incl_scan256(v);
    if (t < nblk) g_boff[t] = incl - v;
}

__global__ void offs_kernel() {
    int i = blockIdx.x * 256 + threadIdx.x;
    int v = (i < NN) ? g_cnt[i] : 0;
    int incl = incl_scan256(v);
    int off = g_boff[blockIdx.x] + incl - v;
    if (i < NN) { g_off[i] = off; g_cur[i] = off; }
}

__global__ void scatter_kernel(const int* __restrict__ ei, const float* __restrict__ eattr) {
    int e = blockIdx.x * blockDim.x + threadIdx.x;
    if (e >= EE) return;
    int s = ei[e];
    int d = ei[EE + e];
    int p = atomicAdd(&g_cur[d], 1);
    g_edge[p] = make_float4(__int_as_float(s),
                            eattr[e * 3 + 0], eattr[e * 3 + 1], eattr[e * 3 + 2]);
}

// ---------------- 3xTF32 tensor-core GEMM (M=64, 2 CTA/SM — frozen config) ----------------
template <int NTW>
__global__ __launch_bounds__(256) void gemm_mma(
    const float* __restrict__ A,
    const uint32_t* __restrict__ P0, const uint32_t* __restrict__ P1,
    float* __restrict__ O0, float* __restrict__ O1,
    const float* __restrict__ stats,
    const float* __restrict__ lnw, const float* __restrict__ lnb,
    const float* __restrict__ bias,
    int nrows, float inv_count)
{
    extern __shared__ float smem[];
    float* Hs = smem;           // hi fragments: 2048 slots x 4 floats
    float* Ls = smem + 8192;    // lo fragments

    float mean = 0.f, rstd = 1.f;
    if (stats) {
        float s = stats[0], q = stats[1];
        mean = s * inv_count;
        float var = q * inv_count - mean * mean;
        rstd = rsqrtf(var + LN_EPS);
    }

    const int tid = threadIdx.x;
    const int row0 = blockIdx.x * 64;
    for (int i = tid; i < 64 * 128; i += 256) {
        int r = i >> 7, c = i & 127;
        int gr = row0 + r;
        float v = (gr < nrows) ? A[gr * 128 + c] : 0.f;
        if (stats) {
            v = (v - mean) * rstd * lnw[c] + lnb[c];
            v = 0.5f * v * (1.f + erff(v * 0.70710678118654752f));
        }
        uint32_t hi = f2tf32(v);
        int kt = c >> 3, tig = c & 3, cq = (c >> 2) & 1;
        int mt = r >> 4, gg = r & 7, rh = (r >> 3) & 1;
        int slot = (((kt * 4 + mt) * 32) + (gg * 4 + tig)) * 4 + (rh + cq * 2);
        Hs[slot] = __uint_as_float(hi);
        Ls[slot] = __uint_as_float(f2tf32(v - __uint_as_float(hi)));
    }
    __syncthreads();

    const int w = tid >> 5, lane = tid & 31;
    const int g = lane >> 2, tig = lane & 3;

    const uint32_t* P;
    int colbase;
    if (NTW == 4) { P = (w < 4) ? P0 : P1; colbase = (w & 3) * 32; }
    else          { P = P0;                colbase = w * 16; }
    const int nt0 = colbase >> 3;

    float acc[4][NTW][4];
    #pragma unroll
    for (int mt = 0; mt < 4; mt++)
        #pragma unroll
        for (int nt = 0; nt < NTW; nt++)
            #pragma unroll
            for (int j = 0; j < 4; j++) acc[mt][nt][j] = 0.f;

    const uint2* Pv = (const uint2*)P;

    #pragma unroll 2
    for (int kt = 0; kt < 16; kt++) {
        float4 ah4[4], al4[4];
        #pragma unroll
        for (int mt = 0; mt < 4; mt++) {
            int off = ((kt * 4 + mt) * 32 + lane) * 4;
            ah4[mt] = *(const float4*)(Hs + off);
            al4[mt] = *(const float4*)(Ls + off);
        }
        uint2 bh[NTW], bl[NTW];
        #pragma unroll
        for (int nt = 0; nt < NTW; nt++) {
            int o = (kt * 16 + nt0 + nt) * 32 + lane;
            bh[nt] = Pv[o];
            bl[nt] = Pv[o + LO_OFF / 2];
        }

        #pragma unroll
        for (int mt = 0; mt < 4; mt++)
            #pragma unroll
            for (int nt = 0; nt < NTW; nt++) {
                mma_tf32(acc[mt][nt], (const uint32_t*)&ah4[mt], (const uint32_t*)&bh[nt]);
                mma_tf32(acc[mt][nt], (const uint32_t*)&ah4[mt], (const uint32_t*)&bl[nt]);
                mma_tf32(acc[mt][nt], (const uint32_t*)&al4[mt], (const uint32_t*)&bh[nt]);
            }
    }

    float* O = (NTW == 4 && w >= 4) ? O1 : O0;
    #pragma unroll
    for (int mt = 0; mt < 4; mt++) {
        int r = row0 + mt * 16 + g;
        #pragma unroll
        for (int nt = 0; nt < NTW; nt++) {
            int col = colbase + nt * 8 + tig * 2;
            float b0 = 0.f, b1 = 0.f;
            if (NTW == 2 && bias) { b0 = bias[col]; b1 = bias[col + 1]; }
            if (r < nrows) {
                O[r * 128 + col]     = acc[mt][nt][0] + b0;
                O[r * 128 + col + 1] = acc[mt][nt][1] + b1;
            }
            if (r + 8 < nrows) {
                O[(r + 8) * 128 + col]     = acc[mt][nt][2] + b0;
                O[(r + 8) * 128 + col + 1] = acc[mt][nt][3] + b1;
            }
        }
    }
}

// ---------------- edge aggregation: 16 lanes/edge, DEPTH-3 pipelined gather ----------------
// warp = 1 node, 2 sub-groups x 4 edge slots in flight (8 edges/warp). Fused stats.
__global__ __launch_bounds__(128, 5) void edge_kernel(
    const float* __restrict__ We,   // [3][128]
    const float* __restrict__ att,  // [4][32] = 128 floats
    float* __restrict__ st)         // stats slot (sum, sumsq)
{
    __shared__ float bsum, bqsum;
    if (threadIdx.x == 0) { bsum = 0.f; bqsum = 0.f; }
    __syncthreads();

    const int gw = (blockIdx.x * 128 + threadIdx.x) >> 5;   // node id (grid exact)
    const int lane = threadIdx.x & 31;
    const int sub = lane >> 4;          // edge slot 0/1
    const int l = lane & 15;            // position within edge
    const unsigned smask = 0xFFFFu << (sub * 16);
    const int c0 = l * 2;               // this lane's float4 chunks: c0, c0+1

    const float4* att4p = (const float4*)att;
    const float4 at0 = att4p[c0],  at1 = att4p[c0 + 1];
    const float4* xrp = (const float4*)(g_xr + gw * 128);
    const float4 xr0 = __ldg(xrp + c0), xr1 = __ldg(xrp + c0 + 1);
    const float4* Wep = (const float4*)We;
    const float4 w00 = __ldg(Wep + c0),      w01 = __ldg(Wep + c0 + 1);
    const float4 w10 = __ldg(Wep + 32 + c0), w11 = __ldg(Wep + 32 + c0 + 1);
    const float4 w20 = __ldg(Wep + 64 + c0), w21 = __ldg(Wep + 64 + c0 + 1);

    float4 acc0 = make_float4(0.f, 0.f, 0.f, 0.f);
    float4 acc1 = make_float4(0.f, 0.f, 0.f, 0.f);
    float s = 0.f;

    const int e0 = g_off[gw], e1 = g_off[gw + 1];

    int e = e0 + sub;
    const float4 z = make_float4(0.f, 0.f, 0.f, 0.f);
    // 3 loaded slots + 1 prefetched in loop (depth 3)
    float aA0 = 0.f, aA1 = 0.f, aA2 = 0.f; float4 xlA0 = z, xlA1 = z;
    float aB0 = 0.f, aB1 = 0.f, aB2 = 0.f; float4 xlB0 = z, xlB1 = z;
    float aC0 = 0.f, aC1 = 0.f, aC2 = 0.f; float4 xlC0 = z, xlC1 = z;
    if (e < e1) {
        float4 r4 = g_edge[e];
        aA0 = r4.y; aA1 = r4.z; aA2 = r4.w;
        const float4* xlp = (const float4*)(g_xl + __float_as_int(r4.x) * 128);
        xlA0 = __ldg(xlp + c0); xlA1 = __ldg(xlp + c0 + 1);
    }
    if (e + 2 < e1) {
        float4 r4 = g_edge[e + 2];
        aB0 = r4.y; aB1 = r4.z; aB2 = r4.w;
        const float4* xlp = (const float4*)(g_xl + __float_as_int(r4.x) * 128);
        xlB0 = __ldg(xlp + c0); xlB1 = __ldg(xlp + c0 + 1);
    }
    if (e + 4 < e1) {
        float4 r4 = g_edge[e + 4];
        aC0 = r4.y; aC1 = r4.z; aC2 = r4.w;
        const float4* xlp = (const float4*)(g_xl + __float_as_int(r4.x) * 128);
        xlC0 = __ldg(xlp + c0); xlC1 = __ldg(xlp + c0 + 1);
    }

    while (e < e1) {
        // prefetch slot D (distance 3)
        const int ed = e + 6;
        float aD0 = 0.f, aD1 = 0.f, aD2 = 0.f; float4 xlD0 = z, xlD1 = z;
        if (ed < e1) {
            float4 r4 = g_edge[ed];
            aD0 = r4.y; aD1 = r4.z; aD2 = r4.w;
            const float4* xlp = (const float4*)(g_xl + __float_as_int(r4.x) * 128);
            xlD0 = __ldg(xlp + c0); xlD1 = __ldg(xlp + c0 + 1);
        }

        float p = 0.f, v;
        v = xlA0.x + xr0.x + aA0 * w00.x + aA1 * w10.x + aA2 * w20.x;
        v = (v > 0.f) ? v : NEG * v; p += v * at0.x;
        v = xlA0.y + xr0.y + aA0 * w00.y + aA1 * w10.y + aA2 * w20.y;
        v = (v > 0.f) ? v : NEG * v; p += v * at0.y;
        v = xlA0.z + xr0.z + aA0 * w00.z + aA1 * w10.z + aA2 * w20.z;
        v = (v > 0.f) ? v : NEG * v; p += v * at0.z;
        v = xlA0.w + xr0.w + aA0 * w00.w + aA1 * w10.w + aA2 * w20.w;
        v = (v > 0.f) ? v : NEG * v; p += v * at0.w;
        v = xlA1.x + xr1.x + aA0 * w01.x + aA1 * w11.x + aA2 * w21.x;
        v = (v > 0.f) ? v : NEG * v; p += v * at1.x;
        v = xlA1.y + xr1.y + aA0 * w01.y + aA1 * w11.y + aA2 * w21.y;
        v = (v > 0.f) ? v : NEG * v; p += v * at1.y;
        v = xlA1.z + xr1.z + aA0 * w01.z + aA1 * w11.z + aA2 * w21.z;
        v = (v > 0.f) ? v : NEG * v; p += v * at1.z;
        v = xlA1.w + xr1.w + aA0 * w01.w + aA1 * w11.w + aA2 * w21.w;
        v = (v > 0.f) ? v : NEG * v; p += v * at1.w;

        p += __shfl_xor_sync(smask, p, 1);
        p += __shfl_xor_sync(smask, p, 2);

        float wg = __expf(p);
        s += wg;
        acc0.x += wg * xlA0.x; acc0.y += wg * xlA0.y;
        acc0.z += wg * xlA0.z; acc0.w += wg * xlA0.w;
        acc1.x += wg * xlA1.x; acc1.y += wg * xlA1.y;
        acc1.z += wg * xlA1.z; acc1.w += wg * xlA1.w;

        aA0 = aB0; aA1 = aB1; aA2 = aB2; xlA0 = xlB0; xlA1 = xlB1;
        aB0 = aC0; aB1 = aC1; aB2 = aC2; xlB0 = xlC0; xlB1 = xlC1;
        aC0 = aD0; aC1 = aD1; aC2 = aD2; xlC0 = xlD0; xlC1 = xlD1;
        e += 2;
    }

    // merge the 2 sub-groups (warp reconverged)
    s += __shfl_xor_sync(0xffffffffu, s, 16);
    acc0.x += __shfl_xor_sync(0xffffffffu, acc0.x, 16);
    acc0.y += __shfl_xor_sync(0xffffffffu, acc0.y, 16);
    acc0.z += __shfl_xor_sync(0xffffffffu, acc0.z, 16);
    acc0.w += __shfl_xor_sync(0xffffffffu, acc0.w, 16);
    acc1.x += __shfl_xor_sync(0xffffffffu, acc1.x, 16);
    acc1.y += __shfl_xor_sync(0xffffffffu, acc1.y, 16);
    acc1.z += __shfl_xor_sync(0xffffffffu, acc1.z, 16);
    acc1.w += __shfl_xor_sync(0xffffffffu, acc1.w, 16);

    float inv = 1.f / (s + 1e-16f);
    float o0 = acc0.x * inv, o1 = acc0.y * inv, o2 = acc0.z * inv, o3 = acc0.w * inv;
    float o4 = acc1.x * inv, o5 = acc1.y * inv, o6 = acc1.z * inv, o7 = acc1.w * inv;

    if (sub == 0) {
        float4* dst = (float4*)(g_agg + gw * 128);
        dst[c0]     = make_float4(o0, o1, o2, o3);
        dst[c0 + 1] = make_float4(o4, o5, o6, o7);
    }

    float ps = o0 + o1 + o2 + o3 + o4 + o5 + o6 + o7;
    float pq = o0*o0 + o1*o1 + o2*o2 + o3*o3 + o4*o4 + o5*o5 + o6*o6 + o7*o7;
    #pragma unroll
    for (int o = 16; o > 0; o >>= 1) {
        ps += __shfl_xor_sync(0xffffffffu, ps, o);
        pq += __shfl_xor_sync(0xffffffffu, pq, o);
    }
    if (lane == 0) {
        atomicAdd(&bsum, ps * 0.5f);
        atomicAdd(&bqsum, pq * 0.5f);
    }
    __syncthreads();
    if (threadIdx.x == 0) {
        atomicAdd(st, bsum);
        atomicAdd(st + 1, bqsum);
    }
}

// ---------------- launch ----------------
extern "C" void kernel_launch(void* const* d_in, const int* in_sizes, int n_in,
                              void* d_out, int out_size)
{
    const float* x     = (const float*)d_in[0];
    const int*   ei    = (const int*)  d_in[1];
    const float* eattr = (const float*)d_in[2];
    const float* Wl    = (const float*)d_in[3];
    const float* Wr    = (const float*)d_in[4];
    const float* We    = (const float*)d_in[5];
    const float* att   = (const float*)d_in[6];
    const float* lnw   = (const float*)d_in[7];
    const float* lnb   = (const float*)d_in[8];
    const float* Wout  = (const float*)d_in[9];
    const float* bout  = (const float*)d_in[10];
    float* out = (float*)d_out;

    float* xl;  cudaGetSymbolAddress((void**)&xl,  g_xl);
    float* xr;  cudaGetSymbolAddress((void**)&xr,  g_xr);
    float* agg; cudaGetSymbolAddress((void**)&agg, g_agg);
    float* st;  cudaGetSymbolAddress((void**)&st,  g_stats);
    uint32_t* P; cudaGetSymbolAddress((void**)&P,  g_wpack);

    const size_t GSMEM = 2 * 8192 * sizeof(float);  // 64 KB fragment-linear A
    cudaFuncSetAttribute(gemm_mma<4>, cudaFuncAttributeMaxDynamicSharedMemorySize, (int)GSMEM);
    cudaFuncSetAttribute(gemm_mma<2>, cudaFuncAttributeMaxDynamicSharedMemorySize, (int)GSMEM);

    const float inv_count = 1.f / (float)(NN * HID);
    const int NB_NODE = (NN + 255) / 256;       // 196
    const int GEMM_BLOCKS = (NN + 63) / 64;     // 782
    const int EDGE_BLOCKS = NN / 4;             // 12500 (4 warps/block, exact)

    // 1: weight pack (+ zero duties)
    pack_kernel<<<(7 * 16384 + 255) / 256, 256>>>(Wl, Wr, Wout, P);
    // 2-3: CSR part 1
    hist_kernel<<<(EE + 255) / 256, 256>>>(ei);
    blocksum_kernel<<<NB_NODE, 256>>>();
    // 4: layer-0 GEMM (independent of CSR) — the launch ncu captures
    gemm_mma<4><<<GEMM_BLOCKS, 256, GSMEM>>>(
        x, P, P + 3 * 16384, xl, xr,
        nullptr, nullptr, nullptr, nullptr, NN, inv_count);
    // 5-7: CSR part 2
    bscan_kernel<<<1, 256>>>(NB_NODE);
    offs_kernel<<<NB_NODE, 256>>>();
    scatter_kernel<<<(EE + 255) / 256, 256>>>(ei, eattr);

    edge_kernel<<<EDGE_BLOCKS, 128>>>(We, att, st);

    for (int l = 1; l < LAY; l++) {
        gemm_mma<4><<<GEMM_BLOCKS, 256, GSMEM>>>(
            agg, P + l * 16384, P + (3 + l) * 16384, xl, xr,
            st + 2 * (l - 1), lnw + 128 * (l - 1), lnb + 128 * (l - 1), nullptr, NN, inv_count);
        edge_kernel<<<EDGE_BLOCKS, 128>>>(We + l * 384, att + l * 128, st + 2 * l);
    }

    gemm_mma<2><<<GEMM_BLOCKS, 256, GSMEM>>>(
        agg, P + 6 * 16384, nullptr, out, nullptr,
        st + 4, lnw + 256, lnb + 256, bout, NN, inv_count);
}

// round 16
// speedup vs baseline: 1.1190x; 1.1190x over previous
#include <cuda_runtime.h>
#include <math.h>
#include <stdint.h>

#define NN 50000
#define EE 800000
#define HID 128
#define NH 4
#define LAY 3
#define NEG 0.2f
#define LN_EPS 1e-5f
#define LO_OFF (7 * 16384)

// ---------------- scratch ----------------
__device__ float  g_xl[NN * HID];
__device__ float  g_xr[NN * HID];
__device__ float  g_agg[NN * HID];
__device__ int    g_cnt[NN];
__device__ int    g_off[NN + 1];
__device__ int    g_cur[NN];
__device__ float4 g_edge[EE];             // {src_bits, a0, a1, a2}
__device__ float  g_stats[6];
__device__ int    g_bsum[256];
__device__ int    g_boff[256];
__device__ uint32_t g_wpack[14 * 16384];  // hi[7 mats] then lo[7 mats], tf32 fragment order

// ---------------- helpers ----------------
__device__ __forceinline__ uint32_t f2tf32(float v) {
    uint32_t o;
    asm("cvt.rna.tf32.f32 %0, %1;" : "=r"(o) : "f"(v));
    return o;
}

__device__ __forceinline__ void mma_tf32(float c[4], const uint32_t a[4], const uint32_t b[2]) {
    asm volatile(
        "mma.sync.aligned.m16n8k8.row.col.f32.tf32.tf32.f32 "
        "{%0,%1,%2,%3}, {%4,%5,%6,%7}, {%8,%9}, {%0,%1,%2,%3};\n"
        : "+f"(c[0]), "+f"(c[1]), "+f"(c[2]), "+f"(c[3])
        : "r"(a[0]), "r"(a[1]), "r"(a[2]), "r"(a[3]), "r"(b[0]), "r"(b[1]));
}

__device__ __forceinline__ int incl_scan256(int v) {
    int lane = threadIdx.x & 31, w = threadIdx.x >> 5;
    #pragma unroll
    for (int o = 1; o < 32; o <<= 1) {
        int n = __shfl_up_sync(0xffffffffu, v, o);
        if (lane >= o) v += n;
    }
    __shared__ int ws[8];
    if (lane == 31) ws[w] = v;
    __syncthreads();
    int add = 0;
    #pragma unroll
    for (int i = 0; i < 8; i++) if (i < w) add += ws[i];
    __syncthreads();
    return v + add;
}

// ---------------- weight pack (tf32 hi/lo, fragment order) + zero duties ----------------
__global__ void pack_kernel(const float* __restrict__ Wl, const float* __restrict__ Wr,
                            const float* __restrict__ Wout, uint32_t* __restrict__ P) {
    int idx = blockIdx.x * 256 + threadIdx.x;
    if (idx < NN) g_cnt[idx] = 0;
    if (idx < 6) g_stats[idx] = 0.f;
    if (idx == 6) g_off[NN] = EE;
    if (idx >= 7 * 16384) return;
    int mat = idx >> 14;
    int r = idx & 16383;
    int kt   = r >> 10;
    int nt   = (r >> 6) & 15;
    int lane = (r >> 1) & 31;
    int reg  = r & 1;
    int k = kt * 8 + (lane & 3) + reg * 4;
    int n = nt * 8 + (lane >> 2);
    const float* W = (mat < 3) ? (Wl + mat * 16384)
                   : (mat < 6) ? (Wr + (mat - 3) * 16384)
                               : Wout;
    float w = W[k * 128 + n];
    uint32_t hi = f2tf32(w);
    P[idx] = hi;
    P[idx + LO_OFF] = f2tf32(w - __uint_as_float(hi));
}

// ---------------- CSR build ----------------
__global__ void hist_kernel(const int* __restrict__ ei) {
    int e = blockIdx.x * blockDim.x + threadIdx.x;
    if (e >= EE) return;
    atomicAdd(&g_cnt[ei[EE + e]], 1);
}

__global__ void blocksum_kernel() {
    __shared__ int sh[256];
    int i = blockIdx.x * 256 + threadIdx.x;
    sh[threadIdx.x] = (i < NN) ? g_cnt[i] : 0;
    __syncthreads();
    for (int d = 128; d > 0; d >>= 1) {
        if (threadIdx.x < d) sh[threadIdx.x] += sh[threadIdx.x + d];
        __syncthreads();
    }
    if (threadIdx.x == 0) g_bsum[blockIdx.x] = sh[0];
}

__global__ void bscan_kernel(int nblk) {
    int t = threadIdx.x;
    int v = (t < nblk) ? g_bsum[t] : 0;
    int incl = incl_scan256(v);
    if (t < nblk) g_boff[t] = incl - v;
}

__global__ void offs_kernel() {
    int i = blockIdx.x * 256 + threadIdx.x;
    int v = (i < NN) ? g_cnt[i] : 0;
    int incl = incl_scan256(v);
    int off = g_boff[blockIdx.x] + incl - v;
    if (i < NN) { g_off[i] = off; g_cur[i] = off; }
}

__global__ void scatter_kernel(const int* __restrict__ ei, const float* __restrict__ eattr) {
    int e = blockIdx.x * blockDim.x + threadIdx.x;
    if (e >= EE) return;
    int s = ei[e];
    int d = ei[EE + e];
    int p = atomicAdd(&g_cur[d], 1);
    g_edge[p] = make_float4(__int_as_float(s),
                            eattr[e * 3 + 0], eattr[e * 3 + 1], eattr[e * 3 + 2]);
}

// ---------------- 3xTF32 tensor-core GEMM (M=64, 2 CTA/SM — frozen config) ----------------
template <int NTW>
__global__ __launch_bounds__(256) void gemm_mma(
    const float* __restrict__ A,
    const uint32_t* __restrict__ P0, const uint32_t* __restrict__ P1,
    float* __restrict__ O0, float* __restrict__ O1,
    const float* __restrict__ stats,
    const float* __restrict__ lnw, const float* __restrict__ lnb,
    const float* __restrict__ bias,
    int nrows, float inv_count)
{
    extern __shared__ float smem[];
    float* Hs = smem;           // hi fragments: 2048 slots x 4 floats
    float* Ls = smem + 8192;    // lo fragments

    float mean = 0.f, rstd = 1.f;
    if (stats) {
        float s = stats[0], q = stats[1];
        mean = s * inv_count;
        float var = q * inv_count - mean * mean;
        rstd = rsqrtf(var + LN_EPS);
    }

    const int tid = threadIdx.x;
    const int row0 = blockIdx.x * 64;
    for (int i = tid; i < 64 * 128; i += 256) {
        int r = i >> 7, c = i & 127;
        int gr = row0 + r;
        float v = (gr < nrows) ? A[gr * 128 + c] : 0.f;
        if (stats) {
            v = (v - mean) * rstd * lnw[c] + lnb[c];
            v = 0.5f * v * (1.f + erff(v * 0.70710678118654752f));
        }
        uint32_t hi = f2tf32(v);
        int kt = c >> 3, tig = c & 3, cq = (c >> 2) & 1;
        int mt = r >> 4, gg = r & 7, rh = (r >> 3) & 1;
        int slot = (((kt * 4 + mt) * 32) + (gg * 4 + tig)) * 4 + (rh + cq * 2);
        Hs[slot] = __uint_as_float(hi);
        Ls[slot] = __uint_as_float(f2tf32(v - __uint_as_float(hi)));
    }
    __syncthreads();

    const int w = tid >> 5, lane = tid & 31;
    const int g = lane >> 2, tig = lane & 3;

    const uint32_t* P;
    int colbase;
    if (NTW == 4) { P = (w < 4) ? P0 : P1; colbase = (w & 3) * 32; }
    else          { P = P0;                colbase = w * 16; }
    const int nt0 = colbase >> 3;

    float acc[4][NTW][4];
    #pragma unroll
    for (int mt = 0; mt < 4; mt++)
        #pragma unroll
        for (int nt = 0; nt < NTW; nt++)
            #pragma unroll
            for (int j = 0; j < 4; j++) acc[mt][nt][j] = 0.f;

    const uint2* Pv = (const uint2*)P;

    #pragma unroll 2
    for (int kt = 0; kt < 16; kt++) {
        float4 ah4[4], al4[4];
        #pragma unroll
        for (int mt = 0; mt < 4; mt++) {
            int off = ((kt * 4 + mt) * 32 + lane) * 4;
            ah4[mt] = *(const float4*)(Hs + off);
            al4[mt] = *(const float4*)(Ls + off);
        }
        uint2 bh[NTW], bl[NTW];
        #pragma unroll
        for (int nt = 0; nt < NTW; nt++) {
            int o = (kt * 16 + nt0 + nt) * 32 + lane;
            bh[nt] = Pv[o];
            bl[nt] = Pv[o + LO_OFF / 2];
        }

        #pragma unroll
        for (int mt = 0; mt < 4; mt++)
            #pragma unroll
            for (int nt = 0; nt < NTW; nt++) {
                mma_tf32(acc[mt][nt], (const uint32_t*)&ah4[mt], (const uint32_t*)&bh[nt]);
                mma_tf32(acc[mt][nt], (const uint32_t*)&ah4[mt], (const uint32_t*)&bl[nt]);
                mma_tf32(acc[mt][nt], (const uint32_t*)&al4[mt], (const uint32_t*)&bh[nt]);
            }
    }

    float* O = (NTW == 4 && w >= 4) ? O1 : O0;
    #pragma unroll
    for (int mt = 0; mt < 4; mt++) {
        int r = row0 + mt * 16 + g;
        #pragma unroll
        for (int nt = 0; nt < NTW; nt++) {
            int col = colbase + nt * 8 + tig * 2;
            float b0 = 0.f, b1 = 0.f;
            if (NTW == 2 && bias) { b0 = bias[col]; b1 = bias[col + 1]; }
            if (r < nrows) {
                O[r * 128 + col]     = acc[mt][nt][0] + b0;
                O[r * 128 + col + 1] = acc[mt][nt][1] + b1;
            }
            if (r + 8 < nrows) {
                O[(r + 8) * 128 + col]     = acc[mt][nt][2] + b0;
                O[(r + 8) * 128 + col + 1] = acc[mt][nt][3] + b1;
            }
        }
    }
}

// ---------------- edge aggregation: 16 lanes/edge, DEPTH-2 pipelined gather ----------------
// warp = 1 node, 2 sub-groups x 3 edge slots in flight. Fused stats. (R14 config — locked)
__global__ __launch_bounds__(128, 5) void edge_kernel(
    const float* __restrict__ We,   // [3][128]
    const float* __restrict__ att,  // [4][32] = 128 floats
    float* __restrict__ st)         // stats slot (sum, sumsq)
{
    __shared__ float bsum, bqsum;
    if (threadIdx.x == 0) { bsum = 0.f; bqsum = 0.f; }
    __syncthreads();

    const int gw = (blockIdx.x * 128 + threadIdx.x) >> 5;   // node id (grid exact)
    const int lane = threadIdx.x & 31;
    const int sub = lane >> 4;          // edge slot 0/1
    const int l = lane & 15;            // position within edge
    const unsigned smask = 0xFFFFu << (sub * 16);
    const int c0 = l * 2;               // this lane's float4 chunks: c0, c0+1

    const float4* att4p = (const float4*)att;
    const float4 at0 = att4p[c0],  at1 = att4p[c0 + 1];
    const float4* xrp = (const float4*)(g_xr + gw * 128);
    const float4 xr0 = __ldg(xrp + c0), xr1 = __ldg(xrp + c0 + 1);
    const float4* Wep = (const float4*)We;
    const float4 w00 = __ldg(Wep + c0),      w01 = __ldg(Wep + c0 + 1);
    const float4 w10 = __ldg(Wep + 32 + c0), w11 = __ldg(Wep + 32 + c0 + 1);
    const float4 w20 = __ldg(Wep + 64 + c0), w21 = __ldg(Wep + 64 + c0 + 1);

    float4 acc0 = make_float4(0.f, 0.f, 0.f, 0.f);
    float4 acc1 = make_float4(0.f, 0.f, 0.f, 0.f);
    float s = 0.f;

    const int e0 = g_off[gw], e1 = g_off[gw + 1];

    int e = e0 + sub;
    const float4 z = make_float4(0.f, 0.f, 0.f, 0.f);
    float4 recA = z, xlA0 = z, xlA1 = z;
    float4 recB = z, xlB0 = z, xlB1 = z;
    if (e < e1) {
        recA = __ldg(&g_edge[e]);
        const float4* xlp = (const float4*)(g_xl + __float_as_int(recA.x) * 128);
        xlA0 = __ldg(xlp + c0);
        xlA1 = __ldg(xlp + c0 + 1);
    }
    if (e + 2 < e1) {
        recB = __ldg(&g_edge[e + 2]);
        const float4* xlp = (const float4*)(g_xl + __float_as_int(recB.x) * 128);
        xlB0 = __ldg(xlp + c0);
        xlB1 = __ldg(xlp + c0 + 1);
    }

    while (e < e1) {
        // prefetch slot C (distance 2)
        const int ec = e + 4;
        float4 recC = z, xlC0 = z, xlC1 = z;
        if (ec < e1) {
            recC = __ldg(&g_edge[ec]);
            const float4* xlp = (const float4*)(g_xl + __float_as_int(recC.x) * 128);
            xlC0 = __ldg(xlp + c0);
            xlC1 = __ldg(xlp + c0 + 1);
        }

        float p = 0.f, v;
        v = xlA0.x + xr0.x + recA.y * w00.x + recA.z * w10.x + recA.w * w20.x;
        v = (v > 0.f) ? v : NEG * v; p += v * at0.x;
        v = xlA0.y + xr0.y + recA.y * w00.y + recA.z * w10.y + recA.w * w20.y;
        v = (v > 0.f) ? v : NEG * v; p += v * at0.y;
        v = xlA0.z + xr0.z + recA.y * w00.z + recA.z * w10.z + recA.w * w20.z;
        v = (v > 0.f) ? v : NEG * v; p += v * at0.z;
        v = xlA0.w + xr0.w + recA.y * w00.w + recA.z * w10.w + recA.w * w20.w;
        v = (v > 0.f) ? v : NEG * v; p += v * at0.w;
        v = xlA1.x + xr1.x + recA.y * w01.x + recA.z * w11.x + recA.w * w21.x;
        v = (v > 0.f) ? v : NEG * v; p += v * at1.x;
        v = xlA1.y + xr1.y + recA.y * w01.y + recA.z * w11.y + recA.w * w21.y;
        v = (v > 0.f) ? v : NEG * v; p += v * at1.y;
        v = xlA1.z + xr1.z + recA.y * w01.z + recA.z * w11.z + recA.w * w21.z;
        v = (v > 0.f) ? v : NEG * v; p += v * at1.z;
        v = xlA1.w + xr1.w + recA.y * w01.w + recA.z * w11.w + recA.w * w21.w;
        v = (v > 0.f) ? v : NEG * v; p += v * at1.w;

        p += __shfl_xor_sync(smask, p, 1);
        p += __shfl_xor_sync(smask, p, 2);

        float wg = __expf(p);
        s += wg;
        acc0.x += wg * xlA0.x; acc0.y += wg * xlA0.y;
        acc0.z += wg * xlA0.z; acc0.w += wg * xlA0.w;
        acc1.x += wg * xlA1.x; acc1.y += wg * xlA1.y;
        acc1.z += wg * xlA1.z; acc1.w += wg * xlA1.w;

        recA = recB; xlA0 = xlB0; xlA1 = xlB1;
        recB = recC; xlB0 = xlC0; xlB1 = xlC1;
        e += 2;
    }

    // merge the 2 sub-groups (warp reconverged)
    s += __shfl_xor_sync(0xffffffffu, s, 16);
    acc0.x += __shfl_xor_sync(0xffffffffu, acc0.x, 16);
    acc0.y += __shfl_xor_sync(0xffffffffu, acc0.y, 16);
    acc0.z += __shfl_xor_sync(0xffffffffu, acc0.z, 16);
    acc0.w += __shfl_xor_sync(0xffffffffu, acc0.w, 16);
    acc1.x += __shfl_xor_sync(0xffffffffu, acc1.x, 16);
    acc1.y += __shfl_xor_sync(0xffffffffu, acc1.y, 16);
    acc1.z += __shfl_xor_sync(0xffffffffu, acc1.z, 16);
    acc1.w += __shfl_xor_sync(0xffffffffu, acc1.w, 16);

    float inv = 1.f / (s + 1e-16f);
    float o0 = acc0.x * inv, o1 = acc0.y * inv, o2 = acc0.z * inv, o3 = acc0.w * inv;
    float o4 = acc1.x * inv, o5 = acc1.y * inv, o6 = acc1.z * inv, o7 = acc1.w * inv;

    if (sub == 0) {
        float4* dst = (float4*)(g_agg + gw * 128);
        dst[c0]     = make_float4(o0, o1, o2, o3);
        dst[c0 + 1] = make_float4(o4, o5, o6, o7);
    }

    float ps = o0 + o1 + o2 + o3 + o4 + o5 + o6 + o7;
    float pq = o0*o0 + o1*o1 + o2*o2 + o3*o3 + o4*o4 + o5*o5 + o6*o6 + o7*o7;
    #pragma unroll
    for (int o = 16; o > 0; o >>= 1) {
        ps += __shfl_xor_sync(0xffffffffu, ps, o);
        pq += __shfl_xor_sync(0xffffffffu, pq, o);
    }
    if (lane == 0) {
        atomicAdd(&bsum, ps * 0.5f);
        atomicAdd(&bqsum, pq * 0.5f);
    }
    __syncthreads();
    if (threadIdx.x == 0) {
        atomicAdd(st, bsum);
        atomicAdd(st + 1, bqsum);
    }
}

// ---------------- launch ----------------
extern "C" void kernel_launch(void* const* d_in, const int* in_sizes, int n_in,
                              void* d_out, int out_size)
{
    const float* x     = (const float*)d_in[0];
    const int*   ei    = (const int*)  d_in[1];
    const float* eattr = (const float*)d_in[2];
    const float* Wl    = (const float*)d_in[3];
    const float* Wr    = (const float*)d_in[4];
    const float* We    = (const float*)d_in[5];
    const float* att   = (const float*)d_in[6];
    const float* lnw   = (const float*)d_in[7];
    const float* lnb   = (const float*)d_in[8];
    const float* Wout  = (const float*)d_in[9];
    const float* bout  = (const float*)d_in[10];
    float* out = (float*)d_out;

    float* xl;  cudaGetSymbolAddress((void**)&xl,  g_xl);
    float* xr;  cudaGetSymbolAddress((void**)&xr,  g_xr);
    float* agg; cudaGetSymbolAddress((void**)&agg, g_agg);
    float* st;  cudaGetSymbolAddress((void**)&st,  g_stats);
    uint32_t* P; cudaGetSymbolAddress((void**)&P,  g_wpack);

    const size_t GSMEM = 2 * 8192 * sizeof(float);  // 64 KB fragment-linear A
    cudaFuncSetAttribute(gemm_mma<4>, cudaFuncAttributeMaxDynamicSharedMemorySize, (int)GSMEM);
    cudaFuncSetAttribute(gemm_mma<2>, cudaFuncAttributeMaxDynamicSharedMemorySize, (int)GSMEM);

    const float inv_count = 1.f / (float)(NN * HID);
    const int NB_NODE = (NN + 255) / 256;       // 196
    const int GEMM_BLOCKS = (NN + 63) / 64;     // 782
    const int EDGE_BLOCKS = NN / 4;             // 12500 (4 warps/block, exact)

    // 1: weight pack (+ zero duties)
    pack_kernel<<<(7 * 16384 + 255) / 256, 256>>>(Wl, Wr, Wout, P);
    // 2-3: CSR part 1
    hist_kernel<<<(EE + 255) / 256, 256>>>(ei);
    blocksum_kernel<<<NB_NODE, 256>>>();
    // 4: layer-0 GEMM (independent of CSR) — the launch ncu captures
    gemm_mma<4><<<GEMM_BLOCKS, 256, GSMEM>>>(
        x, P, P + 3 * 16384, xl, xr,
        nullptr, nullptr, nullptr, nullptr, NN, inv_count);
    // 5-7: CSR part 2
    bscan_kernel<<<1, 256>>>(NB_NODE);
    offs_kernel<<<NB_NODE, 256>>>();
    scatter_kernel<<<(EE + 255) / 256, 256>>>(ei, eattr);

    edge_kernel<<<EDGE_BLOCKS, 128>>>(We, att, st);

    for (int l = 1; l < LAY; l++) {
        gemm_mma<4><<<GEMM_BLOCKS, 256, GSMEM>>>(
            agg, P + l * 16384, P + (3 + l) * 16384, xl, xr,
            st + 2 * (l - 1), lnw + 128 * (l - 1), lnb + 128 * (l - 1), nullptr, NN, inv_count);
        edge_kernel<<<EDGE_BLOCKS, 128>>>(We + l * 384, att + l * 128, st + 2 * l);
    }

    gemm_mma<2><<<GEMM_BLOCKS, 256, GSMEM>>>(
        agg, P + 6 * 16384, nullptr, out, nullptr,
        st + 4, lnw + 256, lnb + 256, bout, NN, inv_count);
}

// round 17
// speedup vs baseline: 1.1923x; 1.0654x over previous
#include <cuda_runtime.h>
#include <math.h>
#include <stdint.h>

#define NN 50000
#define EE 800000
#define HID 128
#define NH 4
#define LAY 3
#define NEG 0.2f
#define LN_EPS 1e-5f

// ---------------- scratch ----------------
__device__ float  g_xl[NN * HID];
__device__ float  g_xr[NN * HID];
__device__ float  g_agg[NN * HID];
__device__ int    g_cnt[NN];
__device__ int    g_off[NN + 1];
__device__ int    g_cur[NN];
__device__ float4 g_edge[EE];             // {src_bits, a0, a1, a2}
__device__ float  g_stats[6];
__device__ int    g_bsum[256];
__device__ int    g_boff[256];
__device__ uint32_t g_wpack[7 * 16384];   // tf32 hi planes only, fragment order

// ---------------- helpers ----------------
__device__ __forceinline__ uint32_t f2tf32(float v) {
    uint32_t o;
    asm("cvt.rna.tf32.f32 %0, %1;" : "=r"(o) : "f"(v));
    return o;
}

__device__ __forceinline__ void mma_tf32(float c[4], const uint32_t a[4], const uint32_t b[2]) {
    asm volatile(
        "mma.sync.aligned.m16n8k8.row.col.f32.tf32.tf32.f32 "
        "{%0,%1,%2,%3}, {%4,%5,%6,%7}, {%8,%9}, {%0,%1,%2,%3};\n"
        : "+f"(c[0]), "+f"(c[1]), "+f"(c[2]), "+f"(c[3])
        : "r"(a[0]), "r"(a[1]), "r"(a[2]), "r"(a[3]), "r"(b[0]), "r"(b[1]));
}

__device__ __forceinline__ int incl_scan256(int v) {
    int lane = threadIdx.x & 31, w = threadIdx.x >> 5;
    #pragma unroll
    for (int o = 1; o < 32; o <<= 1) {
        int n = __shfl_up_sync(0xffffffffu, v, o);
        if (lane >= o) v += n;
    }
    __shared__ int ws[8];
    if (lane == 31) ws[w] = v;
    __syncthreads();
    int add = 0;
    #pragma unroll
    for (int i = 0; i < 8; i++) if (i < w) add += ws[i];
    __syncthreads();
    return v + add;
}

// ---------------- weight pack (tf32 hi, fragment order) + zero duties ----------------
__global__ void pack_kernel(const float* __restrict__ Wl, const float* __restrict__ Wr,
                            const float* __restrict__ Wout, uint32_t* __restrict__ P) {
    int idx = blockIdx.x * 256 + threadIdx.x;
    if (idx < NN) g_cnt[idx] = 0;
    if (idx < 6) g_stats[idx] = 0.f;
    if (idx == 6) g_off[NN] = EE;
    if (idx >= 7 * 16384) return;
    int mat = idx >> 14;
    int r = idx & 16383;
    int kt   = r >> 10;
    int nt   = (r >> 6) & 15;
    int lane = (r >> 1) & 31;
    int reg  = r & 1;
    int k = kt * 8 + (lane & 3) + reg * 4;
    int n = nt * 8 + (lane >> 2);
    const float* W = (mat < 3) ? (Wl + mat * 16384)
                   : (mat < 6) ? (Wr + (mat - 3) * 16384)
                               : Wout;
    P[idx] = f2tf32(W[k * 128 + n]);
}

// ---------------- CSR build ----------------
__global__ void hist_kernel(const int* __restrict__ ei) {
    int e = blockIdx.x * blockDim.x + threadIdx.x;
    if (e >= EE) return;
    atomicAdd(&g_cnt[ei[EE + e]], 1);
}

__global__ void blocksum_kernel() {
    __shared__ int sh[256];
    int i = blockIdx.x * 256 + threadIdx.x;
    sh[threadIdx.x] = (i < NN) ? g_cnt[i] : 0;
    __syncthreads();
    for (int d = 128; d > 0; d >>= 1) {
        if (threadIdx.x < d) sh[threadIdx.x] += sh[threadIdx.x + d];
        __syncthreads();
    }
    if (threadIdx.x == 0) g_bsum[blockIdx.x] = sh[0];
}

__global__ void bscan_kernel(int nblk) {
    int t = threadIdx.x;
    int v = (t < nblk) ? g_bsum[t] : 0;
    int incl = incl_scan256(v);
    if (t < nblk) g_boff[t] = incl - v;
}

__global__ void offs_kernel() {
    int i = blockIdx.x * 256 + threadIdx.x;
    int v = (i < NN) ? g_cnt[i] : 0;
    int incl = incl_scan256(v);
    int off = g_boff[blockIdx.x] + incl - v;
    if (i < NN) { g_off[i] = off; g_cur[i] = off; }
}

__global__ void scatter_kernel(const int* __restrict__ ei, const float* __restrict__ eattr) {
    int e = blockIdx.x * blockDim.x + threadIdx.x;
    if (e >= EE) return;
    int s = ei[e];
    int d = ei[EE + e];
    int p = atomicAdd(&g_cur[d], 1);
    g_edge[p] = make_float4(__int_as_float(s),
                            eattr[e * 3 + 0], eattr[e * 3 + 1], eattr[e * 3 + 2]);
}

// ---------------- 2-term TF32 GEMM: acc = ah*bh + al*bh (B-lo term dropped) ----------------
// M=64, 2 CTA/SM, fragment-linear A in smem.
template <int NTW>
__global__ __launch_bounds__(256) void gemm_mma(
    const float* __restrict__ A,
    const uint32_t* __restrict__ P0, const uint32_t* __restrict__ P1,
    float* __restrict__ O0, float* __restrict__ O1,
    const float* __restrict__ stats,
    const float* __restrict__ lnw, const float* __restrict__ lnb,
    const float* __restrict__ bias,
    int nrows, float inv_count)
{
    extern __shared__ float smem[];
    float* Hs = smem;           // hi fragments: 2048 slots x 4 floats
    float* Ls = smem + 8192;    // lo fragments (A error plane)

    float mean = 0.f, rstd = 1.f;
    if (stats) {
        float s = stats[0], q = stats[1];
        mean = s * inv_count;
        float var = q * inv_count - mean * mean;
        rstd = rsqrtf(var + LN_EPS);
    }

    const int tid = threadIdx.x;
    const int row0 = blockIdx.x * 64;
    for (int i = tid; i < 64 * 128; i += 256) {
        int r = i >> 7, c = i & 127;
        int gr = row0 + r;
        float v = (gr < nrows) ? A[gr * 128 + c] : 0.f;
        if (stats) {
            v = (v - mean) * rstd * lnw[c] + lnb[c];
            v = 0.5f * v * (1.f + erff(v * 0.70710678118654752f));
        }
        uint32_t hi = f2tf32(v);
        int kt = c >> 3, tig = c & 3, cq = (c >> 2) & 1;
        int mt = r >> 4, gg = r & 7, rh = (r >> 3) & 1;
        int slot = (((kt * 4 + mt) * 32) + (gg * 4 + tig)) * 4 + (rh + cq * 2);
        Hs[slot] = __uint_as_float(hi);
        Ls[slot] = __uint_as_float(f2tf32(v - __uint_as_float(hi)));
    }
    __syncthreads();

    const int w = tid >> 5, lane = tid & 31;
    const int g = lane >> 2, tig = lane & 3;

    const uint32_t* P;
    int colbase;
    if (NTW == 4) { P = (w < 4) ? P0 : P1; colbase = (w & 3) * 32; }
    else          { P = P0;                colbase = w * 16; }
    const int nt0 = colbase >> 3;

    float acc[4][NTW][4];
    #pragma unroll
    for (int mt = 0; mt < 4; mt++)
        #pragma unroll
        for (int nt = 0; nt < NTW; nt++)
            #pragma unroll
            for (int j = 0; j < 4; j++) acc[mt][nt][j] = 0.f;

    const uint2* Pv = (const uint2*)P;

    #pragma unroll 2
    for (int kt = 0; kt < 16; kt++) {
        float4 ah4[4], al4[4];
        #pragma unroll
        for (int mt = 0; mt < 4; mt++) {
            int off = ((kt * 4 + mt) * 32 + lane) * 4;
            ah4[mt] = *(const float4*)(Hs + off);
            al4[mt] = *(const float4*)(Ls + off);
        }
        uint2 bh[NTW];
        #pragma unroll
        for (int nt = 0; nt < NTW; nt++)
            bh[nt] = Pv[(kt * 16 + nt0 + nt) * 32 + lane];

        #pragma unroll
        for (int mt = 0; mt < 4; mt++)
            #pragma unroll
            for (int nt = 0; nt < NTW; nt++) {
                mma_tf32(acc[mt][nt], (const uint32_t*)&ah4[mt], (const uint32_t*)&bh[nt]);
                mma_tf32(acc[mt][nt], (const uint32_t*)&al4[mt], (const uint32_t*)&bh[nt]);
            }
    }

    float* O = (NTW == 4 && w >= 4) ? O1 : O0;
    #pragma unroll
    for (int mt = 0; mt < 4; mt++) {
        int r = row0 + mt * 16 + g;
        #pragma unroll
        for (int nt = 0; nt < NTW; nt++) {
            int col = colbase + nt * 8 + tig * 2;
            float b0 = 0.f, b1 = 0.f;
            if (NTW == 2 && bias) { b0 = bias[col]; b1 = bias[col + 1]; }
            if (r < nrows) {
                O[r * 128 + col]     = acc[mt][nt][0] + b0;
                O[r * 128 + col + 1] = acc[mt][nt][1] + b1;
            }
            if (r + 8 < nrows) {
                O[(r + 8) * 128 + col]     = acc[mt][nt][2] + b0;
                O[(r + 8) * 128 + col + 1] = acc[mt][nt][3] + b1;
            }
        }
    }
}

// ---------------- edge aggregation: 16 lanes/edge, DEPTH-2 pipelined gather (locked) ----------------
__global__ __launch_bounds__(128, 5) void edge_kernel(
    const float* __restrict__ We,   // [3][128]
    const float* __restrict__ att,  // [4][32] = 128 floats
    float* __restrict__ st)         // stats slot (sum, sumsq)
{
    __shared__ float bsum, bqsum;
    if (threadIdx.x == 0) { bsum = 0.f; bqsum = 0.f; }
    __syncthreads();

    const int gw = (blockIdx.x * 128 + threadIdx.x) >> 5;   // node id (grid exact)
    const int lane = threadIdx.x & 31;
    const int sub = lane >> 4;
    const int l = lane & 15;
    const unsigned smask = 0xFFFFu << (sub * 16);
    const int c0 = l * 2;

    const float4* att4p = (const float4*)att;
    const float4 at0 = att4p[c0],  at1 = att4p[c0 + 1];
    const float4* xrp = (const float4*)(g_xr + gw * 128);
    const float4 xr0 = __ldg(xrp + c0), xr1 = __ldg(xrp + c0 + 1);
    const float4* Wep = (const float4*)We;
    const float4 w00 = __ldg(Wep + c0),      w01 = __ldg(Wep + c0 + 1);
    const float4 w10 = __ldg(Wep + 32 + c0), w11 = __ldg(Wep + 32 + c0 + 1);
    const float4 w20 = __ldg(Wep + 64 + c0), w21 = __ldg(Wep + 64 + c0 + 1);

    float4 acc0 = make_float4(0.f, 0.f, 0.f, 0.f);
    float4 acc1 = make_float4(0.f, 0.f, 0.f, 0.f);
    float s = 0.f;

    const int e0 = g_off[gw], e1 = g_off[gw + 1];

    int e = e0 + sub;
    const float4 z = make_float4(0.f, 0.f, 0.f, 0.f);
    float4 recA = z, xlA0 = z, xlA1 = z;
    float4 recB = z, xlB0 = z, xlB1 = z;
    if (e < e1) {
        recA = __ldg(&g_edge[e]);
        const float4* xlp = (const float4*)(g_xl + __float_as_int(recA.x) * 128);
        xlA0 = __ldg(xlp + c0);
        xlA1 = __ldg(xlp + c0 + 1);
    }
    if (e + 2 < e1) {
        recB = __ldg(&g_edge[e + 2]);
        const float4* xlp = (const float4*)(g_xl + __float_as_int(recB.x) * 128);
        xlB0 = __ldg(xlp + c0);
        xlB1 = __ldg(xlp + c0 + 1);
    }

    while (e < e1) {
        const int ec = e + 4;
        float4 recC = z, xlC0 = z, xlC1 = z;
        if (ec < e1) {
            recC = __ldg(&g_edge[ec]);
            const float4* xlp = (const float4*)(g_xl + __float_as_int(recC.x) * 128);
            xlC0 = __ldg(xlp + c0);
            xlC1 = __ldg(xlp + c0 + 1);
        }

        float p = 0.f, v;
        v = xlA0.x + xr0.x + recA.y * w00.x + recA.z * w10.x + recA.w * w20.x;
        v = (v > 0.f) ? v : NEG * v; p += v * at0.x;
        v = xlA0.y + xr0.y + recA.y * w00.y + recA.z * w10.y + recA.w * w20.y;
        v = (v > 0.f) ? v : NEG * v; p += v * at0.y;
        v = xlA0.z + xr0.z + recA.y * w00.z + recA.z * w10.z + recA.w * w20.z;
        v = (v > 0.f) ? v : NEG * v; p += v * at0.z;
        v = xlA0.w + xr0.w + recA.y * w00.w + recA.z * w10.w + recA.w * w20.w;
        v = (v > 0.f) ? v : NEG * v; p += v * at0.w;
        v = xlA1.x + xr1.x + recA.y * w01.x + recA.z * w11.x + recA.w * w21.x;
        v = (v > 0.f) ? v : NEG * v; p += v * at1.x;
        v = xlA1.y + xr1.y + recA.y * w01.y + recA.z * w11.y + recA.w * w21.y;
        v = (v > 0.f) ? v : NEG * v; p += v * at1.y;
        v = xlA1.z + xr1.z + recA.y * w01.z + recA.z * w11.z + recA.w * w21.z;
        v = (v > 0.f) ? v : NEG * v; p += v * at1.z;
        v = xlA1.w + xr1.w + recA.y * w01.w + recA.z * w11.w + recA.w * w21.w;
        v = (v > 0.f) ? v : NEG * v; p += v * at1.w;

        p += __shfl_xor_sync(smask, p, 1);
        p += __shfl_xor_sync(smask, p, 2);

        float wg = __expf(p);
        s += wg;
        acc0.x += wg * xlA0.x; acc0.y += wg * xlA0.y;
        acc0.z += wg * xlA0.z; acc0.w += wg * xlA0.w;
        acc1.x += wg * xlA1.x; acc1.y += wg * xlA1.y;
        acc1.z += wg * xlA1.z; acc1.w += wg * xlA1.w;

        recA = recB; xlA0 = xlB0; xlA1 = xlB1;
        recB = recC; xlB0 = xlC0; xlB1 = xlC1;
        e += 2;
    }

    s += __shfl_xor_sync(0xffffffffu, s, 16);
    acc0.x += __shfl_xor_sync(0xffffffffu, acc0.x, 16);
    acc0.y += __shfl_xor_sync(0xffffffffu, acc0.y, 16);
    acc0.z += __shfl_xor_sync(0xffffffffu, acc0.z, 16);
    acc0.w += __shfl_xor_sync(0xffffffffu, acc0.w, 16);
    acc1.x += __shfl_xor_sync(0xffffffffu, acc1.x, 16);
    acc1.y += __shfl_xor_sync(0xffffffffu, acc1.y, 16);
    acc1.z += __shfl_xor_sync(0xffffffffu, acc1.z, 16);
    acc1.w += __shfl_xor_sync(0xffffffffu, acc1.w, 16);

    float inv = 1.f / (s + 1e-16f);
    float o0 = acc0.x * inv, o1 = acc0.y * inv, o2 = acc0.z * inv, o3 = acc0.w * inv;
    float o4 = acc1.x * inv, o5 = acc1.y * inv, o6 = acc1.z * inv, o7 = acc1.w * inv;

    if (sub == 0) {
        float4* dst = (float4*)(g_agg + gw * 128);
        dst[c0]     = make_float4(o0, o1, o2, o3);
        dst[c0 + 1] = make_float4(o4, o5, o6, o7);
    }

    float ps = o0 + o1 + o2 + o3 + o4 + o5 + o6 + o7;
    float pq = o0*o0 + o1*o1 + o2*o2 + o3*o3 + o4*o4 + o5*o5 + o6*o6 + o7*o7;
    #pragma unroll
    for (int o = 16; o > 0; o >>= 1) {
        ps += __shfl_xor_sync(0xffffffffu, ps, o);
        pq += __shfl_xor_sync(0xffffffffu, pq, o);
    }
    if (lane == 0) {
        atomicAdd(&bsum, ps * 0.5f);
        atomicAdd(&bqsum, pq * 0.5f);
    }
    __syncthreads();
    if (threadIdx.x == 0) {
        atomicAdd(st, bsum);
        atomicAdd(st + 1, bqsum);
    }
}

// ---------------- launch ----------------
extern "C" void kernel_launch(void* const* d_in, const int* in_sizes, int n_in,
                              void* d_out, int out_size)
{
    const float* x     = (const float*)d_in[0];
    const int*   ei    = (const int*)  d_in[1];
    const float* eattr = (const float*)d_in[2];
    const float* Wl    = (const float*)d_in[3];
    const float* Wr    = (const float*)d_in[4];
    const float* We    = (const float*)d_in[5];
    const float* att   = (const float*)d_in[6];
    const float* lnw   = (const float*)d_in[7];
    const float* lnb   = (const float*)d_in[8];
    const float* Wout  = (const float*)d_in[9];
    const float* bout  = (const float*)d_in[10];
    float* out = (float*)d_out;

    float* xl;  cudaGetSymbolAddress((void**)&xl,  g_xl);
    float* xr;  cudaGetSymbolAddress((void**)&xr,  g_xr);
    float* agg; cudaGetSymbolAddress((void**)&agg, g_agg);
    float* st;  cudaGetSymbolAddress((void**)&st,  g_stats);
    uint32_t* P; cudaGetSymbolAddress((void**)&P,  g_wpack);

    const size_t GSMEM = 2 * 8192 * sizeof(float);  // 64 KB fragment-linear A (hi+lo)
    cudaFuncSetAttribute(gemm_mma<4>, cudaFuncAttributeMaxDynamicSharedMemorySize, (int)GSMEM);
    cudaFuncSetAttribute(gemm_mma<2>, cudaFuncAttributeMaxDynamicSharedMemorySize, (int)GSMEM);

    const float inv_count = 1.f / (float)(NN * HID);
    const int NB_NODE = (NN + 255) / 256;       // 196
    const int GEMM_BLOCKS = (NN + 63) / 64;     // 782
    const int EDGE_BLOCKS = NN / 4;             // 12500 (4 warps/block, exact)

    // 1: weight pack (+ zero duties)
    pack_kernel<<<(7 * 16384 + 255) / 256, 256>>>(Wl, Wr, Wout, P);
    // 2-3: CSR part 1
    hist_kernel<<<(EE + 255) / 256, 256>>>(ei);
    blocksum_kernel<<<NB_NODE, 256>>>();
    // 4: layer-0 GEMM (independent of CSR) — the launch ncu captures
    gemm_mma<4><<<GEMM_BLOCKS, 256, GSMEM>>>(
        x, P, P + 3 * 16384, xl, xr,
        nullptr, nullptr, nullptr, nullptr, NN, inv_count);
    // 5-7: CSR part 2
    bscan_kernel<<<1, 256>>>(NB_NODE);
    offs_kernel<<<NB_NODE, 256>>>();
    scatter_kernel<<<(EE + 255) / 256, 256>>>(ei, eattr);

    edge_kernel<<<EDGE_BLOCKS, 128>>>(We, att, st);

    for (int l = 1; l < LAY; l++) {
        gemm_mma<4><<<GEMM_BLOCKS, 256, GSMEM>>>(
            agg, P + l * 16384, P + (3 + l) * 16384, xl, xr,
            st + 2 * (l - 1), lnw + 128 * (l - 1), lnb + 128 * (l - 1), nullptr, NN, inv_count);
        edge_kernel<<<EDGE_BLOCKS, 128>>>(We + l * 384, att + l * 128, st + 2 * l);
    }

    gemm_mma<2><<<GEMM_BLOCKS, 256, GSMEM>>>(
        agg, P + 6 * 16384, nullptr, out, nullptr,
        st + 4, lnw + 256, lnb + 256, bout, NN, inv_count);
}